// round 7
// baseline (speedup 1.0000x reference)
#include <cuda_runtime.h>
#include <cstdint>
#include <math.h>

// Bahdanau attention. Shapes fixed:
#define Bsz 64
#define Tt  4096
#define Ee  256      // K of big GEMM
#define Aa  512      // N of big GEMM
#define Hh  512

// ---------------------------------------------------------------------------
// scratch (static device arrays: allocation-free per harness rules)
// ---------------------------------------------------------------------------
__device__ float g_projh[Bsz * Aa];            // 128 KB
__device__ float g_score[Bsz * Tt];            // 1 MB
__device__ float g_W1R[Ee * Aa];               // 512 KB, tf32-rounded, (E,A)
#define TC 16
__device__ float g_ctx_part[Bsz * TC * Ee];    // 1 MB

// ---------------------------------------------------------------------------
// helpers (sm_100 baseline PTX only: mma.sync, cp.async, tanh.approx)
// ---------------------------------------------------------------------------
__device__ __forceinline__ uint32_t smem_u32(const void* p) {
    return (uint32_t)__cvta_generic_to_shared(p);
}
__device__ __forceinline__ uint32_t f2tf32(float x) {
    uint32_t r;
    asm("cvt.rna.tf32.f32 %0, %1;" : "=r"(r) : "f"(x));
    return r;
}
__device__ __forceinline__ float tanh_fast(float x) {
    float y;
    asm("tanh.approx.f32 %0, %1;" : "=f"(y) : "f"(x));
    return y;
}
__device__ __forceinline__ void mma_tf32(float* c, const uint32_t* a, const uint32_t* b) {
    asm volatile(
        "mma.sync.aligned.m16n8k8.row.col.f32.tf32.tf32.f32 "
        "{%0,%1,%2,%3},{%4,%5,%6,%7},{%8,%9},{%0,%1,%2,%3};"
        : "+f"(c[0]), "+f"(c[1]), "+f"(c[2]), "+f"(c[3])
        : "r"(a[0]), "r"(a[1]), "r"(a[2]), "r"(a[3]), "r"(b[0]), "r"(b[1]));
}

#define CP_ASYNC16(dst_u32, src_ptr) \
    asm volatile("cp.async.cg.shared.global [%0], [%1], 16;\n" :: "r"(dst_u32), "l"(src_ptr))
#define CP_COMMIT() asm volatile("cp.async.commit_group;\n")
#define CP_WAIT(n)  asm volatile("cp.async.wait_group %0;\n" :: "n"(n) : "memory")

// ---------------------------------------------------------------------------
// SMEM layout for score kernel
// ---------------------------------------------------------------------------
#define FS_LD   260                         // 260 % 32 == 4 -> conflict-free A frags
#define BS_LD   136                         // 136 % 32 == 8 -> conflict-free B frags
#define SM_A    0                           // 128*260*4 = 133120
#define SM_B(i) (133120 + (i) * 17408)      // 3 x 32*136*4
#define SM_PH   185344                      // 512 floats
#define SM_WV   187392                      // 512 floats
#define SM_SC   189440                      // 128 floats
#define SM_TOTAL 189952

// ---------------------------------------------------------------------------
// Kernel W1R: tf32-round W1 (layout unchanged, (E,A))
// ---------------------------------------------------------------------------
__global__ void w1r_kernel(const float* __restrict__ W1) {
    const int i = blockIdx.x * 256 + threadIdx.x;   // float4 index, 32768 total
    float4 v = ((const float4*)W1)[i];
    v.x = __uint_as_float(f2tf32(v.x));
    v.y = __uint_as_float(f2tf32(v.y));
    v.z = __uint_as_float(f2tf32(v.z));
    v.w = __uint_as_float(f2tf32(v.w));
    ((float4*)g_W1R)[i] = v;
}

// ---------------------------------------------------------------------------
// Kernel projh: g_projh[b][a] = hs[b]·W2[:,a] + b2[a] + b1[a]   (b1 folded)
// ---------------------------------------------------------------------------
__global__ void projh_kernel(const float* __restrict__ hs, const float* __restrict__ W2,
                             const float* __restrict__ b1, const float* __restrict__ b2) {
    __shared__ float sh[Hh];
    const int b = blockIdx.x;
    for (int i = threadIdx.x; i < Hh; i += blockDim.x) sh[i] = hs[b * Hh + i];
    __syncthreads();
    for (int a = threadIdx.x; a < Aa; a += blockDim.x) {
        float acc = 0.f;
        #pragma unroll 8
        for (int h = 0; h < Hh; ++h) acc = fmaf(sh[h], W2[h * Aa + a], acc);
        g_projh[b * Aa + a] = acc + b2[a] + b1[a];
    }
}

// ---------------------------------------------------------------------------
// Kernel score (tf32 mma.sync, 512 threads, 3-deep cp.async pipeline):
//   CTA tile: 128 rows x 512 cols, as 4 N-chunks of 128 cols x 8 K-steps.
//   Warp grid 4M x 4N; per-warp 32x32 (mf=2, nf=4). 4 warps per SMSP.
//   ONE __syncthreads per step. Per-chunk epilogue: tanh.approx + Wv dot.
// ---------------------------------------------------------------------------
__global__ __launch_bounds__(512, 1)
void score_kernel(const float* __restrict__ F, const float* __restrict__ Wv) {
    extern __shared__ __align__(16) char smem[];
    const uint32_t sb = smem_u32(smem);
    float* Fs   = (float*)(smem + SM_A);
    float* s_ph = (float*)(smem + SM_PH);
    float* s_wv = (float*)(smem + SM_WV);
    float* s_sc = (float*)(smem + SM_SC);

    const int tid  = threadIdx.x;
    const int wid  = tid >> 5;
    const int lane = tid & 31;
    const int g    = lane >> 2;      // groupID (row within frag)
    const int ctg  = lane & 3;       // thread-in-group (col within frag)
    const int wm   = wid & 3;        // 4 M-warps (32 rows each)
    const int wn   = wid >> 2;       // 4 N-warps (32 cols each)
    const int m0   = blockIdx.x * 128;
    const int b    = m0 >> 12;       // / Tt

    // ---- prologue: issue copies for step 0 and step 1 (two groups) ----
    #pragma unroll
    for (int p = 0; p < 2; ++p) {
        const int ns = p & 7, nnc = p >> 3;
        const float* src = g_W1R + (size_t)(ns * 32) * Aa + nnc * 128;
        #pragma unroll
        for (int j = 0; j < 2; ++j) {
            const int q   = tid + j * 512;   // 0..1023 float4
            const int row = q >> 5;
            const int c4  = q & 31;
            CP_ASYNC16(sb + SM_B(p) + (uint32_t)(row * BS_LD + c4 * 4) * 4u,
                       src + (size_t)row * Aa + c4 * 4);
        }
        CP_COMMIT();
    }

    // ---- stage A: features 128x256, pre-rounded to tf32 ----
    {
        const float4* src = (const float4*)(F + (size_t)m0 * Ee);
        #pragma unroll
        for (int j = 0; j < 16; ++j) {
            const int q   = tid + j * 512;   // 0..8191 float4
            const int row = q >> 6;
            const int c4  = q & 63;
            float4 v = src[q];
            v.x = __uint_as_float(f2tf32(v.x));
            v.y = __uint_as_float(f2tf32(v.y));
            v.z = __uint_as_float(f2tf32(v.z));
            v.w = __uint_as_float(f2tf32(v.w));
            *(float4*)(&Fs[row * FS_LD + c4 * 4]) = v;
        }
    }
    if (tid < Aa) {
        s_ph[tid] = g_projh[b * Aa + tid];
        s_wv[tid] = Wv[tid];
    }
    if (tid < 128) s_sc[tid] = 0.f;

    float acc[2][4][4];
    #pragma unroll
    for (int mf = 0; mf < 2; ++mf)
        #pragma unroll
        for (int nf = 0; nf < 4; ++nf)
            #pragma unroll
            for (int r = 0; r < 4; ++r) acc[mf][nf][r] = 0.f;

    for (int step = 0; step < 32; ++step) {        // step = nc*8 + s
        const int s = step & 7;
        // wait for this step's copy, then one barrier (visibility + reuse safety)
        if (step < 31) { CP_WAIT(1); } else { CP_WAIT(0); }
        __syncthreads();
        if (step < 30) {   // issue copy of step+2 into buffer consumed at step-1
            const int nx = step + 2;
            const int ns = nx & 7, nnc = nx >> 3;
            const float* src = g_W1R + (size_t)(ns * 32) * Aa + nnc * 128;
            const uint32_t dstb = sb + SM_B(nx % 3);
            #pragma unroll
            for (int j = 0; j < 2; ++j) {
                const int q   = tid + j * 512;
                const int row = q >> 5;
                const int c4  = q & 31;
                CP_ASYNC16(dstb + (uint32_t)(row * BS_LD + c4 * 4) * 4u,
                           src + (size_t)row * Aa + c4 * 4);
            }
            CP_COMMIT();
        }

        const float* cur = (const float*)(smem + SM_B(step % 3));
        #pragma unroll
        for (int kk = 0; kk < 4; ++kk) {
            const int k8 = s * 32 + kk * 8;
            uint32_t afr[2][4];
            #pragma unroll
            for (int mf = 0; mf < 2; ++mf) {
                const float* base = &Fs[(wm * 32 + mf * 16 + g) * FS_LD + k8 + ctg];
                afr[mf][0] = __float_as_uint(base[0]);
                afr[mf][1] = __float_as_uint(base[8 * FS_LD]);
                afr[mf][2] = __float_as_uint(base[4]);
                afr[mf][3] = __float_as_uint(base[8 * FS_LD + 4]);
            }
            uint32_t bfr[4][2];
            #pragma unroll
            for (int nf = 0; nf < 4; ++nf) {
                const float* base = &cur[(kk * 8 + ctg) * BS_LD + wn * 32 + nf * 8 + g];
                bfr[nf][0] = __float_as_uint(base[0]);
                bfr[nf][1] = __float_as_uint(base[4 * BS_LD]);
            }
            #pragma unroll
            for (int mf = 0; mf < 2; ++mf)
                #pragma unroll
                for (int nf = 0; nf < 4; ++nf)
                    mma_tf32(acc[mf][nf], afr[mf], bfr[nf]);
        }

        if (s == 7) {
            // ---- epilogue for this N-chunk ----
            const int nc = step >> 3;
            #pragma unroll
            for (int mf = 0; mf < 2; ++mf) {
                float rs0 = 0.f, rs1 = 0.f;
                #pragma unroll
                for (int nf = 0; nf < 4; ++nf) {
                    const int cb = nc * 128 + wn * 32 + nf * 8 + 2 * ctg;
                    const float ph0 = s_ph[cb], ph1 = s_ph[cb + 1];
                    const float wv0 = s_wv[cb], wv1 = s_wv[cb + 1];
                    rs0 = fmaf(wv0, tanh_fast(acc[mf][nf][0] + ph0), rs0);
                    rs0 = fmaf(wv1, tanh_fast(acc[mf][nf][1] + ph1), rs0);
                    rs1 = fmaf(wv0, tanh_fast(acc[mf][nf][2] + ph0), rs1);
                    rs1 = fmaf(wv1, tanh_fast(acc[mf][nf][3] + ph1), rs1);
                    acc[mf][nf][0] = 0.f; acc[mf][nf][1] = 0.f;
                    acc[mf][nf][2] = 0.f; acc[mf][nf][3] = 0.f;
                }
                rs0 += __shfl_xor_sync(0xffffffff, rs0, 1);
                rs0 += __shfl_xor_sync(0xffffffff, rs0, 2);
                rs1 += __shfl_xor_sync(0xffffffff, rs1, 1);
                rs1 += __shfl_xor_sync(0xffffffff, rs1, 2);
                if (ctg == 0) {
                    const int r0 = wm * 32 + mf * 16 + g;
                    atomicAdd(&s_sc[r0], rs0);
                    atomicAdd(&s_sc[r0 + 8], rs1);
                }
            }
        }
    }

    __syncthreads();
    if (tid < 128) g_score[m0 + tid] = s_sc[tid];
}

// ---------------------------------------------------------------------------
// Kernel softmax over T per batch (1024 threads, shfl reductions)
// ---------------------------------------------------------------------------
__global__ __launch_bounds__(1024)
void softmax_kernel(float* __restrict__ out_w) {
    __shared__ float se[Tt];
    __shared__ float red[32];
    const int b = blockIdx.x;
    const int tid = threadIdx.x;
    const int lane = tid & 31, wrp = tid >> 5;

    float mx = -INFINITY;
    #pragma unroll
    for (int j = 0; j < 4; ++j) {
        const int i = tid + j * 1024;
        const float v = g_score[b * Tt + i];
        se[i] = v;
        mx = fmaxf(mx, v);
    }
    #pragma unroll
    for (int o = 16; o > 0; o >>= 1) mx = fmaxf(mx, __shfl_xor_sync(0xffffffff, mx, o));
    if (lane == 0) red[wrp] = mx;
    __syncthreads();
    if (wrp == 0) {
        mx = red[lane];
        #pragma unroll
        for (int o = 16; o > 0; o >>= 1) mx = fmaxf(mx, __shfl_xor_sync(0xffffffff, mx, o));
        red[lane] = mx;
    }
    __syncthreads();
    mx = red[0];

    float sm = 0.f;
    #pragma unroll
    for (int j = 0; j < 4; ++j) {
        const int i = tid + j * 1024;
        const float e = expf(se[i] - mx);
        se[i] = e;
        sm += e;
    }
    #pragma unroll
    for (int o = 16; o > 0; o >>= 1) sm += __shfl_xor_sync(0xffffffff, sm, o);
    __syncthreads();   // red[] reuse
    if (lane == 0) red[wrp] = sm;
    __syncthreads();
    if (wrp == 0) {
        sm = red[lane];
        #pragma unroll
        for (int o = 16; o > 0; o >>= 1) sm += __shfl_xor_sync(0xffffffff, sm, o);
        red[lane] = sm;
    }
    __syncthreads();
    const float inv = 1.f / red[0];
    #pragma unroll
    for (int j = 0; j < 4; ++j) {
        const int i = tid + j * 1024;
        out_w[b * Tt + i] = se[i] * inv;
    }
}

// ---------------------------------------------------------------------------
// Kernel ctx: partial weighted sums.  grid (TC, B), block 256.
// ---------------------------------------------------------------------------
__global__ void ctx_kernel(const float* __restrict__ F, const float* __restrict__ w) {
    __shared__ float sw[256];
    __shared__ float4 red[256];
    const int tc = blockIdx.x, b = blockIdx.y;
    const int t0 = tc * 256;
    const int tid = threadIdx.x;
    sw[tid] = w[b * Tt + t0 + tid];
    __syncthreads();

    const int c4 = tid & 63, tg = tid >> 6;
    const float4* f = (const float4*)F + ((size_t)b * Tt + t0) * 64;
    float4 acc = make_float4(0.f, 0.f, 0.f, 0.f);
    #pragma unroll 4
    for (int t = tg; t < 256; t += 4) {
        const float wt = sw[t];
        const float4 v = f[(size_t)t * 64 + c4];
        acc.x = fmaf(wt, v.x, acc.x);
        acc.y = fmaf(wt, v.y, acc.y);
        acc.z = fmaf(wt, v.z, acc.z);
        acc.w = fmaf(wt, v.w, acc.w);
    }
    red[tid] = acc;
    __syncthreads();
    if (tg == 0) {
        const float4 a1 = red[c4 + 64], a2 = red[c4 + 128], a3 = red[c4 + 192];
        acc = red[c4];
        acc.x += a1.x + a2.x + a3.x;
        acc.y += a1.y + a2.y + a3.y;
        acc.z += a1.z + a2.z + a3.z;
        acc.w += a1.w + a2.w + a3.w;
        ((float4*)g_ctx_part)[(size_t)(b * TC + tc) * 64 + c4] = acc;
    }
}

__global__ void ctx_reduce_kernel(float* __restrict__ out_ctx) {
    const int b = blockIdx.x, e = threadIdx.x;
    float a = 0.f;
    #pragma unroll
    for (int j = 0; j < TC; ++j) a += g_ctx_part[(size_t)(b * TC + j) * Ee + e];
    out_ctx[b * Ee + e] = a;
}

// ---------------------------------------------------------------------------
// launch
// ---------------------------------------------------------------------------
extern "C" void kernel_launch(void* const* d_in, const int* in_sizes, int n_in,
                              void* d_out, int out_size) {
    const float* F  = (const float*)d_in[0];  // features (B,T,E)
    const float* hs = (const float*)d_in[1];  // hidden_state (B,H)
    const float* W1 = (const float*)d_in[2];  // (E,A)
    const float* b1 = (const float*)d_in[3];  // (A,)
    const float* W2 = (const float*)d_in[4];  // (H,A)
    const float* b2 = (const float*)d_in[5];  // (A,)
    const float* Wv = (const float*)d_in[6];  // (A,1)
    // d_in[7] = bv: softmax-invariant, unused.
    (void)in_sizes; (void)n_in; (void)out_size;

    float* out     = (float*)d_out;
    float* out_ctx = out;                 // context_vector (B,E)
    float* out_w   = out + Bsz * Ee;      // attention_weights (B,T,1)

    cudaFuncSetAttribute(score_kernel, cudaFuncAttributeMaxDynamicSharedMemorySize, SM_TOTAL);

    w1r_kernel<<<(Ee * Aa / 4) / 256, 256>>>(W1);
    projh_kernel<<<Bsz, 512>>>(hs, W2, b1, b2);
    score_kernel<<<(Bsz * Tt) / 128, 512, SM_TOTAL>>>(F, Wv);
    softmax_kernel<<<Bsz, 1024>>>(out_w);
    ctx_kernel<<<dim3(TC, Bsz), 256>>>(F, out_w);
    ctx_reduce_kernel<<<Bsz, 256>>>(out_ctx);
}

// round 9
// speedup vs baseline: 1.8637x; 1.8637x over previous
#include <cuda_runtime.h>
#include <cuda_fp16.h>
#include <cstdint>
#include <math.h>

// Bahdanau attention. Shapes fixed:
#define Bsz 64
#define Tt  4096
#define Ee  256      // K of big GEMM
#define Aa  512      // N of big GEMM
#define Hh  512

// ---------------------------------------------------------------------------
// scratch (static device arrays: allocation-free per harness rules)
// ---------------------------------------------------------------------------
__device__ float  g_projh[Bsz * Aa];           // 128 KB
__device__ float  g_score[Bsz * Tt];           // 1 MB
__device__ __half g_W1Th[Aa * Ee];             // 256 KB, fp16, [A][E] (K-contig)
#define TC 16
__device__ float  g_ctx_part[Bsz * TC * Ee];   // 1 MB

// ---------------------------------------------------------------------------
// helpers (sm_100 baseline PTX only: mma.sync fp16, cp.async, tanh.approx)
// ---------------------------------------------------------------------------
__device__ __forceinline__ uint32_t smem_u32(const void* p) {
    return (uint32_t)__cvta_generic_to_shared(p);
}
__device__ __forceinline__ float tanh_fast(float x) {
    float y;
    asm("tanh.approx.f32 %0, %1;" : "=f"(y) : "f"(x));
    return y;
}
// m16n8k16 fp16 inputs, fp32 accumulate
__device__ __forceinline__ void mma_f16(float* c, const uint32_t* a, const uint32_t* b) {
    asm volatile(
        "mma.sync.aligned.m16n8k16.row.col.f32.f16.f16.f32 "
        "{%0,%1,%2,%3},{%4,%5,%6,%7},{%8,%9},{%0,%1,%2,%3};"
        : "+f"(c[0]), "+f"(c[1]), "+f"(c[2]), "+f"(c[3])
        : "r"(a[0]), "r"(a[1]), "r"(a[2]), "r"(a[3]), "r"(b[0]), "r"(b[1]));
}

#define CP_ASYNC16(dst_u32, src_ptr) \
    asm volatile("cp.async.cg.shared.global [%0], [%1], 16;\n" :: "r"(dst_u32), "l"(src_ptr))
#define CP_COMMIT() asm volatile("cp.async.commit_group;\n")
#define CP_WAIT(n)  asm volatile("cp.async.wait_group %0;\n" :: "n"(n) : "memory")

// ---------------------------------------------------------------------------
// SMEM layout for score kernel (all fp16 operands; sizes in BYTES)
//   Fs2: 128 rows x 132 half2 (K=256 -> 128 half2 + pad4) = 67584
//   Bs : 2 buffers x [128 n-rows x 36 half2 (64 k + pad)] = 2 x 18432
// ---------------------------------------------------------------------------
#define FS2_LD  132                     // half2 stride; 132%32==4 -> conflict-free
#define BS2_LD  36                      // half2 stride; 36%32==4  -> conflict-free
#define SM_A    0
#define SM_B(i) (67584 + (i) * 18432)
#define SM_PH   104448                  // 512 floats
#define SM_WV   106496                  // 512 floats
#define SM_SC   108544                  // 128 floats
#define SM_TOTAL 109056                 // x2 CTAs = 218112 <= smem/SM

// ---------------------------------------------------------------------------
// Kernel w1t: W1 (E,A) fp32 -> g_W1Th [A][E] fp16 (rn)
// ---------------------------------------------------------------------------
__global__ void w1t_kernel(const float* __restrict__ W1) {
    __shared__ float t[32][33];
    const int a0 = blockIdx.x * 32, e0 = blockIdx.y * 32;
    t[threadIdx.y][threadIdx.x] = W1[(e0 + threadIdx.y) * Aa + a0 + threadIdx.x];
    __syncthreads();
    g_W1Th[(a0 + threadIdx.y) * Ee + e0 + threadIdx.x] =
        __float2half_rn(t[threadIdx.x][threadIdx.y]);
}

// ---------------------------------------------------------------------------
// Kernel projh: g_projh[b][a] = hs[b]·W2[:,a] + b2[a] + b1[a]   (b1 folded)
// ---------------------------------------------------------------------------
__global__ void projh_kernel(const float* __restrict__ hs, const float* __restrict__ W2,
                             const float* __restrict__ b1, const float* __restrict__ b2) {
    __shared__ float sh[Hh];
    const int b = blockIdx.x;
    for (int i = threadIdx.x; i < Hh; i += blockDim.x) sh[i] = hs[b * Hh + i];
    __syncthreads();
    for (int a = threadIdx.x; a < Aa; a += blockDim.x) {
        float acc = 0.f;
        #pragma unroll 8
        for (int h = 0; h < Hh; ++h) acc = fmaf(sh[h], W2[h * Aa + a], acc);
        g_projh[b * Aa + a] = acc + b2[a] + b1[a];
    }
}

// ---------------------------------------------------------------------------
// Kernel score (fp16 m16n8k16 mma.sync, 256 threads, 2 CTAs/SM):
//   CTA tile 128 rows x 512 cols: 4 N-chunks(128) x 4 K-chunks(64).
//   A = features 128x256 fp16 (half2), resident. B = W1Th chunks, dbl-buffered.
//   Warp grid 4M x 2N; per-warp 32x64 (mf=2, nf=8); 16 mma per K16-substep.
//   Per-N-chunk epilogue: score[row] += sum_c Wv[c]*tanh.approx(D+projh).
// ---------------------------------------------------------------------------
__global__ __launch_bounds__(256, 2)
void score_kernel(const float* __restrict__ F, const float* __restrict__ Wv) {
    extern __shared__ __align__(16) char smem[];
    const uint32_t sb = smem_u32(smem);
    const __half2* Fs2 = (const __half2*)(smem + SM_A);
    float* s_ph = (float*)(smem + SM_PH);
    float* s_wv = (float*)(smem + SM_WV);
    float* s_sc = (float*)(smem + SM_SC);

    const int tid  = threadIdx.x;
    const int wid  = tid >> 5;
    const int lane = tid & 31;
    const int g    = lane >> 2;      // groupID (row within frag)
    const int ctg  = lane & 3;       // thread-in-group
    const int wm   = wid & 3;        // 4 M-warps (32 rows each)
    const int wn   = wid >> 2;       // 2 N-warps (64 cols each)
    const int m0   = blockIdx.x * 128;
    const int b    = m0 >> 12;       // / Tt

    // ---- prologue: issue B copy for step 0 (nc=0, kc=0) ----
    {
        #pragma unroll
        for (int j = 0; j < 4; ++j) {
            const int q   = tid + j * 256;   // 0..1023 cp16 ops
            const int n   = q >> 3;          // 8 x 16B per 64-fp16 row
            const int c16 = q & 7;
            CP_ASYNC16(sb + SM_B(0) + (uint32_t)(n * BS2_LD * 4 + c16 * 16),
                       (const char*)g_W1Th + (size_t)n * 512 + c16 * 16);
        }
        CP_COMMIT();
    }

    // ---- stage A: features 128x256 fp32 -> fp16 half2 ----
    {
        const float4* src = (const float4*)(F + (size_t)m0 * Ee);
        #pragma unroll
        for (int jj = 0; jj < 16; ++jj) {
            const int q8  = tid + jj * 256;  // float8 index, 0..4095
            const int row = q8 >> 5;         // 32 float8 per 256-col row
            const int c8  = q8 & 31;
            const float4 v0 = src[q8 * 2];
            const float4 v1 = src[q8 * 2 + 1];
            __half2 h[4];
            h[0] = __floats2half2_rn(v0.x, v0.y);
            h[1] = __floats2half2_rn(v0.z, v0.w);
            h[2] = __floats2half2_rn(v1.x, v1.y);
            h[3] = __floats2half2_rn(v1.z, v1.w);
            *(uint4*)(smem + SM_A + row * (FS2_LD * 4) + c8 * 16) = *(const uint4*)h;
        }
    }
    if (tid < 256) {
        s_ph[tid] = g_projh[b * Aa + tid];
        s_ph[tid + 256] = g_projh[b * Aa + tid + 256];
        s_wv[tid] = Wv[tid];
        s_wv[tid + 256] = Wv[tid + 256];
    }
    if (tid < 128) s_sc[tid] = 0.f;

    float acc[2][8][4];
    #pragma unroll
    for (int mf = 0; mf < 2; ++mf)
        #pragma unroll
        for (int nf = 0; nf < 8; ++nf)
            #pragma unroll
            for (int r = 0; r < 4; ++r) acc[mf][nf][r] = 0.f;

    int buf = 0;
    for (int step = 0; step < 16; ++step) {        // step = nc*4 + kc
        const int kc = step & 3;
        __syncthreads();   // all warps done reading buf^1 (A staged at step 0)
        if (step < 15) {   // issue copy of step+1 into buf^1
            const int nx  = step + 1;
            const int nkc = nx & 3, nnc = nx >> 2;
            const char* src = (const char*)g_W1Th + (size_t)nnc * 128 * 512 + nkc * 128;
            const uint32_t dstb = sb + SM_B(buf ^ 1);
            #pragma unroll
            for (int j = 0; j < 4; ++j) {
                const int q   = tid + j * 256;
                const int n   = q >> 3;
                const int c16 = q & 7;
                CP_ASYNC16(dstb + (uint32_t)(n * BS2_LD * 4 + c16 * 16),
                           src + (size_t)n * 512 + c16 * 16);
            }
            CP_COMMIT();
            CP_WAIT(1);    // this step's copy (older group) complete
        } else {
            CP_WAIT(0);
        }
        __syncthreads();

        const __half2* cur = (const __half2*)(smem + SM_B(buf));
        #pragma unroll
        for (int tt = 0; tt < 4; ++tt) {           // K16 substeps within kc
            const int ak2 = kc * 32 + tt * 8;      // A k2 base (global)
            const int bk2 = tt * 8;                // B k2 base (chunk-local)
            uint32_t afr[2][4];
            #pragma unroll
            for (int mf = 0; mf < 2; ++mf) {
                const __half2* base = &Fs2[(wm * 32 + mf * 16 + g) * FS2_LD + ak2 + ctg];
                afr[mf][0] = *(const uint32_t*)(base);
                afr[mf][1] = *(const uint32_t*)(base + 8 * FS2_LD);
                afr[mf][2] = *(const uint32_t*)(base + 4);
                afr[mf][3] = *(const uint32_t*)(base + 8 * FS2_LD + 4);
            }
            uint32_t bfr[8][2];
            #pragma unroll
            for (int nf = 0; nf < 8; ++nf) {
                const __half2* base = &cur[(wn * 64 + nf * 8 + g) * BS2_LD + bk2 + ctg];
                bfr[nf][0] = *(const uint32_t*)(base);
                bfr[nf][1] = *(const uint32_t*)(base + 4);
            }
            #pragma unroll
            for (int mf = 0; mf < 2; ++mf)
                #pragma unroll
                for (int nf = 0; nf < 8; ++nf)
                    mma_f16(acc[mf][nf], afr[mf], bfr[nf]);
        }

        if (kc == 3) {
            // ---- epilogue for this N-chunk ----
            const int nc = step >> 2;
            #pragma unroll
            for (int mf = 0; mf < 2; ++mf) {
                float rs0 = 0.f, rs1 = 0.f;
                #pragma unroll
                for (int nf = 0; nf < 8; ++nf) {
                    const int cb = nc * 128 + wn * 64 + nf * 8 + 2 * ctg;
                    const float ph0 = s_ph[cb], ph1 = s_ph[cb + 1];
                    const float wv0 = s_wv[cb], wv1 = s_wv[cb + 1];
                    rs0 = fmaf(wv0, tanh_fast(acc[mf][nf][0] + ph0), rs0);
                    rs0 = fmaf(wv1, tanh_fast(acc[mf][nf][1] + ph1), rs0);
                    rs1 = fmaf(wv0, tanh_fast(acc[mf][nf][2] + ph0), rs1);
                    rs1 = fmaf(wv1, tanh_fast(acc[mf][nf][3] + ph1), rs1);
                    acc[mf][nf][0] = 0.f; acc[mf][nf][1] = 0.f;
                    acc[mf][nf][2] = 0.f; acc[mf][nf][3] = 0.f;
                }
                rs0 += __shfl_xor_sync(0xffffffff, rs0, 1);
                rs0 += __shfl_xor_sync(0xffffffff, rs0, 2);
                rs1 += __shfl_xor_sync(0xffffffff, rs1, 1);
                rs1 += __shfl_xor_sync(0xffffffff, rs1, 2);
                if (ctg == 0) {
                    const int r0 = wm * 32 + mf * 16 + g;
                    atomicAdd(&s_sc[r0], rs0);
                    atomicAdd(&s_sc[r0 + 8], rs1);
                }
            }
        }
        buf ^= 1;
    }

    __syncthreads();
    if (tid < 128) g_score[m0 + tid] = s_sc[tid];
}

// ---------------------------------------------------------------------------
// Kernel softmax over T per batch (1024 threads, shfl reductions)
// ---------------------------------------------------------------------------
__global__ __launch_bounds__(1024)
void softmax_kernel(float* __restrict__ out_w) {
    __shared__ float se[Tt];
    __shared__ float red[32];
    const int b = blockIdx.x;
    const int tid = threadIdx.x;
    const int lane = tid & 31, wrp = tid >> 5;

    float mx = -INFINITY;
    #pragma unroll
    for (int j = 0; j < 4; ++j) {
        const int i = tid + j * 1024;
        const float v = g_score[b * Tt + i];
        se[i] = v;
        mx = fmaxf(mx, v);
    }
    #pragma unroll
    for (int o = 16; o > 0; o >>= 1) mx = fmaxf(mx, __shfl_xor_sync(0xffffffff, mx, o));
    if (lane == 0) red[wrp] = mx;
    __syncthreads();
    if (wrp == 0) {
        mx = red[lane];
        #pragma unroll
        for (int o = 16; o > 0; o >>= 1) mx = fmaxf(mx, __shfl_xor_sync(0xffffffff, mx, o));
        red[lane] = mx;
    }
    __syncthreads();
    mx = red[0];

    float sm = 0.f;
    #pragma unroll
    for (int j = 0; j < 4; ++j) {
        const int i = tid + j * 1024;
        const float e = expf(se[i] - mx);
        se[i] = e;
        sm += e;
    }
    #pragma unroll
    for (int o = 16; o > 0; o >>= 1) sm += __shfl_xor_sync(0xffffffff, sm, o);
    __syncthreads();   // red[] reuse
    if (lane == 0) red[wrp] = sm;
    __syncthreads();
    if (wrp == 0) {
        sm = red[lane];
        #pragma unroll
        for (int o = 16; o > 0; o >>= 1) sm += __shfl_xor_sync(0xffffffff, sm, o);
        red[lane] = sm;
    }
    __syncthreads();
    const float inv = 1.f / red[0];
    #pragma unroll
    for (int j = 0; j < 4; ++j) {
        const int i = tid + j * 1024;
        out_w[b * Tt + i] = se[i] * inv;
    }
}

// ---------------------------------------------------------------------------
// Kernel ctx: partial weighted sums.  grid (TC, B), block 256.
// ---------------------------------------------------------------------------
__global__ void ctx_kernel(const float* __restrict__ F, const float* __restrict__ w) {
    __shared__ float sw[256];
    __shared__ float4 red[256];
    const int tc = blockIdx.x, b = blockIdx.y;
    const int t0 = tc * 256;
    const int tid = threadIdx.x;
    sw[tid] = w[b * Tt + t0 + tid];
    __syncthreads();

    const int c4 = tid & 63, tg = tid >> 6;
    const float4* f = (const float4*)F + ((size_t)b * Tt + t0) * 64;
    float4 acc = make_float4(0.f, 0.f, 0.f, 0.f);
    #pragma unroll 4
    for (int t = tg; t < 256; t += 4) {
        const float wt = sw[t];
        const float4 v = f[(size_t)t * 64 + c4];
        acc.x = fmaf(wt, v.x, acc.x);
        acc.y = fmaf(wt, v.y, acc.y);
        acc.z = fmaf(wt, v.z, acc.z);
        acc.w = fmaf(wt, v.w, acc.w);
    }
    red[tid] = acc;
    __syncthreads();
    if (tg == 0) {
        const float4 a1 = red[c4 + 64], a2 = red[c4 + 128], a3 = red[c4 + 192];
        acc = red[c4];
        acc.x += a1.x + a2.x + a3.x;
        acc.y += a1.y + a2.y + a3.y;
        acc.z += a1.z + a2.z + a3.z;
        acc.w += a1.w + a2.w + a3.w;
        ((float4*)g_ctx_part)[(size_t)(b * TC + tc) * 64 + c4] = acc;
    }
}

__global__ void ctx_reduce_kernel(float* __restrict__ out_ctx) {
    const int b = blockIdx.x, e = threadIdx.x;
    float a = 0.f;
    #pragma unroll
    for (int j = 0; j < TC; ++j) a += g_ctx_part[(size_t)(b * TC + j) * Ee + e];
    out_ctx[b * Ee + e] = a;
}

// ---------------------------------------------------------------------------
// launch
// ---------------------------------------------------------------------------
extern "C" void kernel_launch(void* const* d_in, const int* in_sizes, int n_in,
                              void* d_out, int out_size) {
    const float* F  = (const float*)d_in[0];  // features (B,T,E)
    const float* hs = (const float*)d_in[1];  // hidden_state (B,H)
    const float* W1 = (const float*)d_in[2];  // (E,A)
    const float* b1 = (const float*)d_in[3];  // (A,)
    const float* W2 = (const float*)d_in[4];  // (H,A)
    const float* b2 = (const float*)d_in[5];  // (A,)
    const float* Wv = (const float*)d_in[6];  // (A,1)
    // d_in[7] = bv: softmax-invariant, unused.
    (void)in_sizes; (void)n_in; (void)out_size;

    float* out     = (float*)d_out;
    float* out_ctx = out;                 // context_vector (B,E)
    float* out_w   = out + Bsz * Ee;      // attention_weights (B,T,1)

    cudaFuncSetAttribute(score_kernel, cudaFuncAttributeMaxDynamicSharedMemorySize, SM_TOTAL);

    w1t_kernel<<<dim3(Aa / 32, Ee / 32), dim3(32, 32)>>>(W1);
    projh_kernel<<<Bsz, 512>>>(hs, W2, b1, b2);
    score_kernel<<<(Bsz * Tt) / 128, 256, SM_TOTAL>>>(F, Wv);
    softmax_kernel<<<Bsz, 1024>>>(out_w);
    ctx_kernel<<<dim3(TC, Bsz), 256>>>(F, out_w);
    ctx_reduce_kernel<<<Bsz, 256>>>(out_ctx);
}

// round 10
// speedup vs baseline: 1.9605x; 1.0520x over previous
#include <cuda_runtime.h>
#include <cuda_fp16.h>
#include <cstdint>
#include <math.h>

// Bahdanau attention. Shapes fixed:
#define Bsz 64
#define Tt  4096
#define Ee  256      // K of big GEMM
#define Aa  512      // N of big GEMM
#define Hh  512

// ---------------------------------------------------------------------------
// scratch (static device arrays: allocation-free per harness rules)
// ---------------------------------------------------------------------------
__device__ float  g_projh[Bsz * Aa];             // 128 KB
__device__ float  g_score[Bsz * Tt];             // 1 MB
__device__ __half g_W1Th[Aa * Ee];               // 256 KB, fp16, [A][E]
__device__ float  g_ctx_part[(Bsz * Tt / 128) * Ee];  // 2048 x 256 = 2 MB
__device__ float  g_cta_meta[(Bsz * Tt / 128) * 2];   // (m_cta, sum_cta)
__device__ float  g_meta[Bsz * 2];               // (M, denom) per batch

// ---------------------------------------------------------------------------
// helpers (sm_100 baseline PTX only: mma.sync fp16, cp.async, tanh.approx)
// ---------------------------------------------------------------------------
__device__ __forceinline__ uint32_t smem_u32(const void* p) {
    return (uint32_t)__cvta_generic_to_shared(p);
}
__device__ __forceinline__ float tanh_fast(float x) {
    float y;
    asm("tanh.approx.f32 %0, %1;" : "=f"(y) : "f"(x));
    return y;
}
__device__ __forceinline__ void mma_f16(float* c, const uint32_t* a, const uint32_t* b) {
    asm volatile(
        "mma.sync.aligned.m16n8k16.row.col.f32.f16.f16.f32 "
        "{%0,%1,%2,%3},{%4,%5,%6,%7},{%8,%9},{%0,%1,%2,%3};"
        : "+f"(c[0]), "+f"(c[1]), "+f"(c[2]), "+f"(c[3])
        : "r"(a[0]), "r"(a[1]), "r"(a[2]), "r"(a[3]), "r"(b[0]), "r"(b[1]));
}

#define CP_ASYNC16(dst_u32, src_ptr) \
    asm volatile("cp.async.cg.shared.global [%0], [%1], 16;\n" :: "r"(dst_u32), "l"(src_ptr))
#define CP_COMMIT() asm volatile("cp.async.commit_group;\n")
#define CP_WAIT(n)  asm volatile("cp.async.wait_group %0;\n" :: "n"(n) : "memory")

// ---------------------------------------------------------------------------
// SMEM layout for score kernel (bytes)
// ---------------------------------------------------------------------------
#define FS2_LD  132                     // half2 row stride; %32==4 -> conflict-free
#define BS2_LD  36                      // half2 row stride; %32==4 -> conflict-free
#define SM_A    0                       // 128*132*4 = 67584
#define SM_B(i) (67584 + (i) * 18432)   // 2 x 128*36*4
#define SM_PH   104448                  // 512 floats
#define SM_WV   106496                  // 512 floats
#define SM_SC   108544                  // 128 floats
#define SM_RED  109056                  // 8 floats
#define SM_TOTAL 109088                 // x2 CTAs/SM fits

// ---------------------------------------------------------------------------
// Kernel w1t: W1 (E,A) fp32 -> g_W1Th [A][E] fp16 (rn)
// ---------------------------------------------------------------------------
__global__ void w1t_kernel(const float* __restrict__ W1) {
    __shared__ float t[32][33];
    const int a0 = blockIdx.x * 32, e0 = blockIdx.y * 32;
    t[threadIdx.y][threadIdx.x] = W1[(e0 + threadIdx.y) * Aa + a0 + threadIdx.x];
    __syncthreads();
    g_W1Th[(a0 + threadIdx.y) * Ee + e0 + threadIdx.x] =
        __float2half_rn(t[threadIdx.x][threadIdx.y]);
}

// ---------------------------------------------------------------------------
// Kernel projh: g_projh[b][a] = hs[b]·W2[:,a] + b2[a] + b1[a]   (b1 folded)
// ---------------------------------------------------------------------------
__global__ void projh_kernel(const float* __restrict__ hs, const float* __restrict__ W2,
                             const float* __restrict__ b1, const float* __restrict__ b2) {
    __shared__ float sh[Hh];
    const int b = blockIdx.x;
    for (int i = threadIdx.x; i < Hh; i += blockDim.x) sh[i] = hs[b * Hh + i];
    __syncthreads();
    for (int a = threadIdx.x; a < Aa; a += blockDim.x) {
        float acc = 0.f;
        #pragma unroll 8
        for (int h = 0; h < Hh; ++h) acc = fmaf(sh[h], W2[h * Aa + a], acc);
        g_projh[b * Aa + a] = acc + b2[a] + b1[a];
    }
}

// ---------------------------------------------------------------------------
// Kernel score (fp16 m16n8k16 mma.sync, 256 threads, 2 CTAs/SM) + fused
// per-CTA online-softmax context partial (uses resident fp16 F tile).
// ---------------------------------------------------------------------------
__global__ __launch_bounds__(256, 2)
void score_kernel(const float* __restrict__ F, const float* __restrict__ Wv) {
    extern __shared__ __align__(16) char smem[];
    const uint32_t sb = smem_u32(smem);
    const __half2* Fs2 = (const __half2*)(smem + SM_A);
    float* s_ph  = (float*)(smem + SM_PH);
    float* s_wv  = (float*)(smem + SM_WV);
    float* s_sc  = (float*)(smem + SM_SC);
    float* s_red = (float*)(smem + SM_RED);

    const int tid  = threadIdx.x;
    const int wid  = tid >> 5;
    const int lane = tid & 31;
    const int g    = lane >> 2;
    const int ctg  = lane & 3;
    const int wm   = wid & 3;        // 4 M-warps
    const int wn   = wid >> 2;       // 2 N-warps
    const int m0   = blockIdx.x * 128;
    const int b    = m0 >> 12;

    // ---- prologue: issue B copy for step 0 ----
    {
        #pragma unroll
        for (int j = 0; j < 4; ++j) {
            const int q   = tid + j * 256;
            const int n   = q >> 3;
            const int c16 = q & 7;
            CP_ASYNC16(sb + SM_B(0) + (uint32_t)(n * BS2_LD * 4 + c16 * 16),
                       (const char*)g_W1Th + (size_t)n * 512 + c16 * 16);
        }
        CP_COMMIT();
    }

    // ---- stage A: features 128x256 fp32 -> fp16 half2 ----
    {
        const float4* src = (const float4*)(F + (size_t)m0 * Ee);
        #pragma unroll
        for (int jj = 0; jj < 16; ++jj) {
            const int q8  = tid + jj * 256;
            const int row = q8 >> 5;
            const int c8  = q8 & 31;
            const float4 v0 = src[q8 * 2];
            const float4 v1 = src[q8 * 2 + 1];
            __half2 h[4];
            h[0] = __floats2half2_rn(v0.x, v0.y);
            h[1] = __floats2half2_rn(v0.z, v0.w);
            h[2] = __floats2half2_rn(v1.x, v1.y);
            h[3] = __floats2half2_rn(v1.z, v1.w);
            *(uint4*)(smem + SM_A + row * (FS2_LD * 4) + c8 * 16) = *(const uint4*)h;
        }
    }
    if (tid < 256) {
        s_ph[tid] = g_projh[b * Aa + tid];
        s_ph[tid + 256] = g_projh[b * Aa + tid + 256];
        s_wv[tid] = Wv[tid];
        s_wv[tid + 256] = Wv[tid + 256];
    }
    if (tid < 128) s_sc[tid] = 0.f;

    float acc[2][8][4];
    #pragma unroll
    for (int mf = 0; mf < 2; ++mf)
        #pragma unroll
        for (int nf = 0; nf < 8; ++nf)
            #pragma unroll
            for (int r = 0; r < 4; ++r) acc[mf][nf][r] = 0.f;

    int buf = 0;
    for (int step = 0; step < 16; ++step) {        // step = nc*4 + kc
        const int kc = step & 3;
        __syncthreads();
        if (step < 15) {
            const int nx  = step + 1;
            const int nkc = nx & 3, nnc = nx >> 2;
            const char* src = (const char*)g_W1Th + (size_t)nnc * 128 * 512 + nkc * 128;
            const uint32_t dstb = sb + SM_B(buf ^ 1);
            #pragma unroll
            for (int j = 0; j < 4; ++j) {
                const int q   = tid + j * 256;
                const int n   = q >> 3;
                const int c16 = q & 7;
                CP_ASYNC16(dstb + (uint32_t)(n * BS2_LD * 4 + c16 * 16),
                           src + (size_t)n * 512 + c16 * 16);
            }
            CP_COMMIT();
            CP_WAIT(1);
        } else {
            CP_WAIT(0);
        }
        __syncthreads();

        const __half2* cur = (const __half2*)(smem + SM_B(buf));
        #pragma unroll
        for (int tt = 0; tt < 4; ++tt) {
            const int ak2 = kc * 32 + tt * 8;
            const int bk2 = tt * 8;
            uint32_t afr[2][4];
            #pragma unroll
            for (int mf = 0; mf < 2; ++mf) {
                const __half2* base = &Fs2[(wm * 32 + mf * 16 + g) * FS2_LD + ak2 + ctg];
                afr[mf][0] = *(const uint32_t*)(base);
                afr[mf][1] = *(const uint32_t*)(base + 8 * FS2_LD);
                afr[mf][2] = *(const uint32_t*)(base + 4);
                afr[mf][3] = *(const uint32_t*)(base + 8 * FS2_LD + 4);
            }
            uint32_t bfr[8][2];
            #pragma unroll
            for (int nf = 0; nf < 8; ++nf) {
                const __half2* base = &cur[(wn * 64 + nf * 8 + g) * BS2_LD + bk2 + ctg];
                bfr[nf][0] = *(const uint32_t*)(base);
                bfr[nf][1] = *(const uint32_t*)(base + 4);
            }
            #pragma unroll
            for (int mf = 0; mf < 2; ++mf)
                #pragma unroll
                for (int nf = 0; nf < 8; ++nf)
                    mma_f16(acc[mf][nf], afr[mf], bfr[nf]);
        }

        if (kc == 3) {
            const int nc = step >> 2;
            #pragma unroll
            for (int mf = 0; mf < 2; ++mf) {
                float rs0 = 0.f, rs1 = 0.f;
                #pragma unroll
                for (int nf = 0; nf < 8; ++nf) {
                    const int cb = nc * 128 + wn * 64 + nf * 8 + 2 * ctg;
                    const float ph0 = s_ph[cb], ph1 = s_ph[cb + 1];
                    const float wv0 = s_wv[cb], wv1 = s_wv[cb + 1];
                    rs0 = fmaf(wv0, tanh_fast(acc[mf][nf][0] + ph0), rs0);
                    rs0 = fmaf(wv1, tanh_fast(acc[mf][nf][1] + ph1), rs0);
                    rs1 = fmaf(wv0, tanh_fast(acc[mf][nf][2] + ph0), rs1);
                    rs1 = fmaf(wv1, tanh_fast(acc[mf][nf][3] + ph1), rs1);
                    acc[mf][nf][0] = 0.f; acc[mf][nf][1] = 0.f;
                    acc[mf][nf][2] = 0.f; acc[mf][nf][3] = 0.f;
                }
                rs0 += __shfl_xor_sync(0xffffffff, rs0, 1);
                rs0 += __shfl_xor_sync(0xffffffff, rs0, 2);
                rs1 += __shfl_xor_sync(0xffffffff, rs1, 1);
                rs1 += __shfl_xor_sync(0xffffffff, rs1, 2);
                if (ctg == 0) {
                    const int r0 = wm * 32 + mf * 16 + g;
                    atomicAdd(&s_sc[r0], rs0);
                    atomicAdd(&s_sc[r0 + 8], rs1);
                }
            }
        }
        buf ^= 1;
    }

    __syncthreads();   // s_sc complete; Fs2 still resident

    // ---- fused per-CTA softmax partial + context partial ----
    if (tid < 128) g_score[m0 + tid] = s_sc[tid];

    // max over 128 scores
    if (tid < 128) {
        float v = s_sc[tid];
        #pragma unroll
        for (int o = 16; o > 0; o >>= 1) v = fmaxf(v, __shfl_xor_sync(0xffffffff, v, o));
        if (lane == 0) s_red[wid] = v;
    }
    __syncthreads();
    if (tid == 0)
        s_red[4] = fmaxf(fmaxf(s_red[0], s_red[1]), fmaxf(s_red[2], s_red[3]));
    __syncthreads();
    const float Mc = s_red[4];

    // exp in place + sum
    if (tid < 128) {
        float e = expf(s_sc[tid] - Mc);
        s_sc[tid] = e;
        #pragma unroll
        for (int o = 16; o > 0; o >>= 1) e += __shfl_xor_sync(0xffffffff, e, o);
        if (lane == 0) s_red[wid] = e;
    }
    __syncthreads();
    if (tid == 0) {
        g_cta_meta[blockIdx.x * 2]     = Mc;
        g_cta_meta[blockIdx.x * 2 + 1] = s_red[0] + s_red[1] + s_red[2] + s_red[3];
    }

    // ctx partial: thread = column e (256 threads), loop 128 rows
    {
        float cacc = 0.f;
        const int e2 = tid >> 1, hi = tid & 1;
        #pragma unroll 8
        for (int t = 0; t < 128; ++t) {
            const __half2 h = Fs2[t * FS2_LD + e2];
            const float f = hi ? __high2float(h) : __low2float(h);
            cacc = fmaf(s_sc[t], f, cacc);
        }
        g_ctx_part[(size_t)blockIdx.x * Ee + tid] = cacc;
    }
}

// ---------------------------------------------------------------------------
// Kernel combine: merge 32 CTA partials per batch (exact LSE rescale).
//   grid 64, block 256. Writes out_ctx and g_meta (M, denom).
// ---------------------------------------------------------------------------
__global__ __launch_bounds__(256)
void combine_kernel(float* __restrict__ out_ctx) {
    __shared__ float sm_m[32], sm_s[32], sm_sc[32];
    const int b = blockIdx.x, tid = threadIdx.x;
    if (tid < 32) {
        sm_m[tid] = g_cta_meta[(b * 32 + tid) * 2];
        sm_s[tid] = g_cta_meta[(b * 32 + tid) * 2 + 1];
    }
    __syncthreads();
    float M = -INFINITY;
    #pragma unroll
    for (int j = 0; j < 32; ++j) M = fmaxf(M, sm_m[j]);
    if (tid < 32) sm_sc[tid] = expf(sm_m[tid] - M);
    __syncthreads();
    float denom = 0.f;
    #pragma unroll
    for (int j = 0; j < 32; ++j) denom = fmaf(sm_sc[j], sm_s[j], denom);

    float acc = 0.f;
    #pragma unroll 4
    for (int j = 0; j < 32; ++j)
        acc = fmaf(sm_sc[j], g_ctx_part[(size_t)(b * 32 + j) * Ee + tid], acc);
    out_ctx[b * Ee + tid] = acc / denom;

    if (tid == 0) {
        g_meta[b * 2]     = M;
        g_meta[b * 2 + 1] = denom;
    }
}

// ---------------------------------------------------------------------------
// Kernel weights: out_w[b][t] = exp(score - M) / denom.  grid 64, block 1024.
// ---------------------------------------------------------------------------
__global__ __launch_bounds__(1024)
void weights_kernel(float* __restrict__ out_w) {
    const int b = blockIdx.x, tid = threadIdx.x;
    const float M   = g_meta[b * 2];
    const float inv = 1.f / g_meta[b * 2 + 1];
    #pragma unroll
    for (int j = 0; j < 4; ++j) {
        const int i = tid + j * 1024;
        out_w[b * Tt + i] = expf(g_score[b * Tt + i] - M) * inv;
    }
}

// ---------------------------------------------------------------------------
// launch
// ---------------------------------------------------------------------------
extern "C" void kernel_launch(void* const* d_in, const int* in_sizes, int n_in,
                              void* d_out, int out_size) {
    const float* F  = (const float*)d_in[0];  // features (B,T,E)
    const float* hs = (const float*)d_in[1];  // hidden_state (B,H)
    const float* W1 = (const float*)d_in[2];  // (E,A)
    const float* b1 = (const float*)d_in[3];  // (A,)
    const float* W2 = (const float*)d_in[4];  // (H,A)
    const float* b2 = (const float*)d_in[5];  // (A,)
    const float* Wv = (const float*)d_in[6];  // (A,1)
    // d_in[7] = bv: softmax-invariant, unused.
    (void)in_sizes; (void)n_in; (void)out_size;

    float* out     = (float*)d_out;
    float* out_ctx = out;                 // context_vector (B,E)
    float* out_w   = out + Bsz * Ee;      // attention_weights (B,T,1)

    cudaFuncSetAttribute(score_kernel, cudaFuncAttributeMaxDynamicSharedMemorySize, SM_TOTAL);

    w1t_kernel<<<dim3(Aa / 32, Ee / 32), dim3(32, 32)>>>(W1);
    projh_kernel<<<Bsz, 512>>>(hs, W2, b1, b2);
    score_kernel<<<(Bsz * Tt) / 128, 256, SM_TOTAL>>>(F, Wv);
    combine_kernel<<<Bsz, 256>>>(out_ctx);
    weights_kernel<<<Bsz, 1024>>>(out_w);
}